// round 2
// baseline (speedup 1.0000x reference)
#include <cuda_runtime.h>
#include <cstdint>

// Problem constants (fixed by the reference)
#define BB 128
#define TT 2048
#define II 32
#define HH 64
constexpr int NROWS = BB * TT;            // 262144
constexpr int NELEM = NROWS * HH;         // 16,777,216 per plane

// Scratch (device-global: no runtime allocation allowed)
__device__ float g_xw0[NELEM];   // forward-dir input projection  [B,T,H]
__device__ float g_xw1[NELEM];   // backward-dir input projection
__device__ float g_h0[NELEM];    // forward hidden states
__device__ float g_h1[NELEM];    // backward hidden states

typedef unsigned long long u64;

// ---- packed f32x2 helpers (Blackwell sm_103a) ------------------------------
__device__ __forceinline__ u64 pk2(float lo, float hi) {
    u64 r; asm("mov.b64 %0, {%1, %2};" : "=l"(r) : "f"(lo), "f"(hi)); return r;
}
__device__ __forceinline__ void upk2(u64 v, float& lo, float& hi) {
    asm("mov.b64 {%0, %1}, %2;" : "=f"(lo), "=f"(hi) : "l"(v));
}
__device__ __forceinline__ u64 ffma2(u64 a, u64 b, u64 c) {
    u64 d; asm("fma.rn.f32x2 %0, %1, %2, %3;" : "=l"(d) : "l"(a), "l"(b), "l"(c)); return d;
}

// ============================================================================
// Kernel 1: input projection, both directions.
// xw[d][b,t,j] = sum_i x[b,t,i] * W_ih_d[j,i] + b_ih_d[j] + b_hh_d[j]
// Thread map: j = tx&63, dir = (tx>>6)&1, slot = tx>>7 (2 slots x 4 rows).
// Weights (32 floats) held packed in registers; x rows staged in SMEM.
// ============================================================================
__global__ __launch_bounds__(256) void proj_kernel(
    const float* __restrict__ x,
    const float* __restrict__ Wihf, const float* __restrict__ Wihb,
    const float* __restrict__ bihf, const float* __restrict__ bhhf,
    const float* __restrict__ bihb, const float* __restrict__ bhhb)
{
    __shared__ __align__(16) float sx[8][32];

    const int tx   = threadIdx.x;
    const int j    = tx & 63;
    const int dir  = (tx >> 6) & 1;
    const int slot = tx >> 7;                 // 0..1

    const float* W  = dir ? Wihb : Wihf;
    const float bsum = dir ? (bihb[j] + bhhb[j]) : (bihf[j] + bhhf[j]);

    u64 w[16];
#pragma unroll
    for (int m = 0; m < 16; m++)
        w[m] = pk2(W[j * II + 2 * m], W[j * II + 2 * m + 1]);

    float* out = dir ? g_xw1 : g_xw0;

    const int ntiles = NROWS / 8;
    for (int tile = blockIdx.x; tile < ntiles; tile += gridDim.x) {
        const int row0 = tile * 8;
        __syncthreads();
        {   // stage 8 rows of x (8*32 floats), fully coalesced
            int r = tx >> 5, i = tx & 31;
            sx[r][i] = x[(row0 + r) * II + i];
        }
        __syncthreads();
#pragma unroll
        for (int rr = 0; rr < 4; rr++) {
            const int r = slot * 4 + rr;
            const ulonglong2* xp = reinterpret_cast<const ulonglong2*>(&sx[r][0]);
            u64 acc = 0;  // bit pattern of {0.f, 0.f}
#pragma unroll
            for (int m = 0; m < 8; m++) {
                ulonglong2 xv = xp[m];
                acc = ffma2(w[2 * m],     xv.x, acc);
                acc = ffma2(w[2 * m + 1], xv.y, acc);
            }
            float lo, hi; upk2(acc, lo, hi);
            out[(row0 + r) * HH + j] = lo + hi + bsum;
        }
    }
}

// ============================================================================
// Kernel 2: the recurrent scan, both directions.
// h_t = relu(xw_t + h_{t-1} @ W_hh^T), h_{-1} = 0; backward dir runs t reversed.
// Fast path (W_hh == I, checked exactly at runtime): 16384 independent scalar
// chains h = relu(xw + h). General path: per-(b,dir) cooperative matvec with
// W rows in registers and h in SMEM.
// Grid: 128 blocks x 128 threads. blk>>6 = dir, blk&63 = batch pair.
// ============================================================================
__global__ __launch_bounds__(128) void scan_kernel(
    const float* __restrict__ Whhf, const float* __restrict__ Whhb)
{
    const int blk  = blockIdx.x;
    const int dir  = blk >> 6;
    const int bpr  = blk & 63;
    const int tx   = threadIdx.x;
    const int g    = tx >> 6;         // which batch of the pair
    const int j    = tx & 63;
    const int b    = bpr * 2 + g;

    const float* W = dir ? Whhb : Whhf;

    __shared__ int sOK;
    if (tx == 0) sOK = 1;
    __syncthreads();
    {
        bool ok = true;
#pragma unroll
        for (int k = 0; k < HH; k++) {
            float want = (k == j) ? 1.0f : 0.0f;
            if (W[j * HH + k] != want) ok = false;
        }
        if (!ok) atomicAnd(&sOK, 0);
    }
    __syncthreads();

    const float* xw   = dir ? g_xw1 : g_xw0;
    float*       hout = dir ? g_h1  : g_h0;
    const int    base = b * TT * HH + j;

    if (sOK) {
        // --- identity fast path: independent elementwise chain -------------
        float h = 0.0f;
        if (dir == 0) {
            int p = base;
            for (int t = 0; t < TT; t += 8) {
#pragma unroll
                for (int u = 0; u < 8; u++) {
                    float v = xw[p + u * HH];
                    h = fmaxf(v + h, 0.0f);
                    hout[p + u * HH] = h;
                }
                p += 8 * HH;
            }
        } else {
            int p = base + (TT - 1) * HH;
            for (int t = 0; t < TT; t += 8) {
#pragma unroll
                for (int u = 0; u < 8; u++) {
                    float v = xw[p - u * HH];
                    h = fmaxf(v + h, 0.0f);
                    hout[p - u * HH] = h;
                }
                p -= 8 * HH;
            }
        }
    } else {
        // --- general fallback: cooperative 64x64 matvec per step -----------
        __shared__ float sh[2][HH];
        float wrow[HH];
#pragma unroll
        for (int k = 0; k < HH; k++) wrow[k] = W[j * HH + k];
        sh[g][j] = 0.0f;
        __syncthreads();
        for (int t = 0; t < TT; t++) {
            const int tt  = dir ? (TT - 1 - t) : t;
            const int idx = base + tt * HH;
            float acc = xw[idx];
#pragma unroll
            for (int k = 0; k < HH; k++) acc += wrow[k] * sh[g][k];
            acc = fmaxf(acc, 0.0f);
            __syncthreads();
            sh[g][j] = acc;
            __syncthreads();
            hout[idx] = acc;
        }
    }
}

// ============================================================================
// Kernel 3: MLP head.
// out[r] = ff1_b + sum_j ff1[j] * leaky(ff0_b[j] + sum_k ff0[j,k]*hcat[r,k])
// hcat[r] = [hf[r] ; hb[r]] (128 wide).
// Thread map (256 thr): kseg = tx&3 (32-wide k segment), jp = tx>>2 → j pair
// (2j, 2j+1). Weights: 64 floats/thread packed in regs. h rows staged in SMEM,
// read as broadcast LDS.128. kseg partials combined via shfl.xor(1,2);
// j-reduction via shfl.xor(4,8,16) — each of the 8 jp in a warp is counted
// exactly once (bits 0,1 are held fixed), so NO rescaling.
// ============================================================================
__global__ __launch_bounds__(256) void mlp_kernel(
    const float* __restrict__ ff0w, const float* __restrict__ ff0b,
    const float* __restrict__ ff1w, const float* __restrict__ ff1b,
    float* __restrict__ out)
{
    __shared__ __align__(16) float shh[8][128];
    __shared__ float sPart[8][8];

    const int tx   = threadIdx.x;
    const int kseg = tx & 3;
    const int jp   = tx >> 2;       // 0..63
    const int j0   = jp * 2, j1 = j0 + 1;
    const int kb   = kseg * 32;
    const int warp = tx >> 5, lane = tx & 31;

    u64 wa[16], wb[16];
#pragma unroll
    for (int m = 0; m < 16; m++) {
        wa[m] = pk2(ff0w[j0 * 128 + kb + 2 * m], ff0w[j0 * 128 + kb + 2 * m + 1]);
        wb[m] = pk2(ff0w[j1 * 128 + kb + 2 * m], ff0w[j1 * 128 + kb + 2 * m + 1]);
    }
    const float b00 = ff0b[j0], b01 = ff0b[j1];
    const float f10 = ff1w[j0], f11 = ff1w[j1];
    const float f1b = ff1b[0];

    const int ntiles = NROWS / 8;
    for (int tile = blockIdx.x; tile < ntiles; tile += gridDim.x) {
        const int row0 = tile * 8;
        __syncthreads();
#pragma unroll
        for (int q = 0; q < 4; q++) {
            int l = tx + q * 256;
            int r = l >> 7, c = l & 127;
            shh[r][c] = (c < 64) ? g_h0[(row0 + r) * HH + c]
                                 : g_h1[(row0 + r) * HH + (c - 64)];
        }
        __syncthreads();
#pragma unroll 1
        for (int r = 0; r < 8; r++) {
            const ulonglong2* hp = reinterpret_cast<const ulonglong2*>(&shh[r][kb]);
            u64 acc0 = 0, acc1 = 0;
#pragma unroll
            for (int m = 0; m < 8; m++) {
                ulonglong2 hv = hp[m];
                acc0 = ffma2(wa[2 * m],     hv.x, acc0);
                acc0 = ffma2(wa[2 * m + 1], hv.y, acc0);
                acc1 = ffma2(wb[2 * m],     hv.x, acc1);
                acc1 = ffma2(wb[2 * m + 1], hv.y, acc1);
            }
            float l0, h0, l1, h1;
            upk2(acc0, l0, h0); upk2(acc1, l1, h1);
            float z0 = l0 + h0, z1 = l1 + h1;
            // combine the 4 k-segments (lane bits 0,1)
            z0 += __shfl_xor_sync(0xffffffffu, z0, 1);
            z0 += __shfl_xor_sync(0xffffffffu, z0, 2);
            z1 += __shfl_xor_sync(0xffffffffu, z1, 1);
            z1 += __shfl_xor_sync(0xffffffffu, z1, 2);
            z0 += b00; z1 += b01;
            float y0 = z0 > 0.0f ? z0 : 0.01f * z0;
            float y1 = z1 > 0.0f ? z1 : 0.01f * z1;
            float y = f10 * y0 + f11 * y1;
            // reduce over the 8 distinct j-pairs in this warp (bits 2..4)
            y += __shfl_xor_sync(0xffffffffu, y, 4);
            y += __shfl_xor_sync(0xffffffffu, y, 8);
            y += __shfl_xor_sync(0xffffffffu, y, 16);
            if (lane == 0) sPart[warp][r] = y;
        }
        __syncthreads();
        if (tx < 8) {
            float s = 0.0f;
#pragma unroll
            for (int w = 0; w < 8; w++) s += sPart[w][tx];
            out[row0 + tx] = s + f1b;   // each j counted exactly once — no scale
        }
    }
}

// ============================================================================
extern "C" void kernel_launch(void* const* d_in, const int* in_sizes, int n_in,
                              void* d_out, int out_size)
{
    const float* x    = (const float*)d_in[0];
    const float* Wihf = (const float*)d_in[1];
    const float* Whhf = (const float*)d_in[2];
    const float* bihf = (const float*)d_in[3];
    const float* bhhf = (const float*)d_in[4];
    const float* Wihb = (const float*)d_in[5];
    const float* Whhb = (const float*)d_in[6];
    const float* bihb = (const float*)d_in[7];
    const float* bhhb = (const float*)d_in[8];
    const float* ff0w = (const float*)d_in[9];
    const float* ff0b = (const float*)d_in[10];
    const float* ff1w = (const float*)d_in[11];
    const float* ff1b = (const float*)d_in[12];

    proj_kernel<<<2048, 256>>>(x, Wihf, Wihb, bihf, bhhf, bihb, bhhb);
    scan_kernel<<<128, 128>>>(Whhf, Whhb);
    mlp_kernel<<<2048, 256>>>(ff0w, ff0b, ff1w, ff1b, (float*)d_out);
}

// round 3
// speedup vs baseline: 1.7955x; 1.7955x over previous
#include <cuda_runtime.h>
#include <cstdint>

// Problem constants (fixed by the reference)
#define BB 128
#define TT 2048
#define II 32
#define HH 64
constexpr int NROWS = BB * TT;            // 262144
constexpr int NELEM = NROWS * HH;         // 16,777,216 per plane

// Scratch (device globals — no runtime allocation allowed).
// xw planes are T-MAJOR: xw[b][j][t]   (per dir)
// h  planes are T-MAJOR: h [b][j][t]   (per dir)
__device__ float g_xw0[NELEM];
__device__ float g_xw1[NELEM];
__device__ float g_h0[NELEM];
__device__ float g_h1[NELEM];

typedef unsigned long long u64;

// ---- packed f32x2 helpers (Blackwell sm_103a) ------------------------------
__device__ __forceinline__ u64 pk2(float lo, float hi) {
    u64 r; asm("mov.b64 %0, {%1, %2};" : "=l"(r) : "f"(lo), "f"(hi)); return r;
}
__device__ __forceinline__ void upk2(u64 v, float& lo, float& hi) {
    asm("mov.b64 {%0, %1}, %2;" : "=f"(lo), "=f"(hi) : "l"(v));
}
__device__ __forceinline__ u64 ffma2(u64 a, u64 b, u64 c) {
    u64 d; asm("fma.rn.f32x2 %0, %1, %2, %3;" : "=l"(d) : "l"(a), "l"(b), "l"(c)); return d;
}

// ============================================================================
// Kernel 1: input projection, both directions, t-major output.
// xw[d][b][j][t] = sum_i x[b,t,i]*W_ih_d[j,i] + b_ih_d[j] + b_hh_d[j]
// Grid: 8192 blocks = (b, 32-t tile). Block: 256 thr = 8 warps.
// Warp w: dir = w>>2, t-group tq = w&3 (8 t's). Lane = j-pair (2 j's).
// x tile staged in SMEM, read as warp-broadcast LDS.128 (t warp-uniform).
// Each thread: 2 j x 8 t results -> 4 contiguous float4 stores.
// ============================================================================
__global__ __launch_bounds__(256) void proj_kernel(
    const float* __restrict__ x,
    const float* __restrict__ Wihf, const float* __restrict__ Wihb,
    const float* __restrict__ bihf, const float* __restrict__ bhhf,
    const float* __restrict__ bihb, const float* __restrict__ bhhb)
{
    __shared__ __align__(16) float sx[32][32];

    const int tile = blockIdx.x;
    const int b    = tile >> 6;            // 64 tiles per batch
    const int t0   = (tile & 63) * 32;
    const int tx   = threadIdx.x;
    const int w    = tx >> 5;
    const int lane = tx & 31;
    const int dir  = w >> 2;
    const int tq   = w & 3;
    const int j0   = lane * 2, j1 = j0 + 1;

    // stage x: 32 rows x 32 cols, coalesced float4
    {
        int r = tx >> 3, c4 = (tx & 7) * 4;
        *(float4*)&sx[r][c4] =
            *(const float4*)&x[(size_t)(b * TT + t0 + r) * II + c4];
    }

    const float* W = dir ? Wihb : Wihf;
    u64 w0[16], w1[16];
#pragma unroll
    for (int m = 0; m < 16; m++) {
        w0[m] = pk2(W[j0 * II + 2 * m], W[j0 * II + 2 * m + 1]);
        w1[m] = pk2(W[j1 * II + 2 * m], W[j1 * II + 2 * m + 1]);
    }
    const float bs0 = dir ? (bihb[j0] + bhhb[j0]) : (bihf[j0] + bhhf[j0]);
    const float bs1 = dir ? (bihb[j1] + bhhb[j1]) : (bihf[j1] + bhhf[j1]);

    __syncthreads();

    float r0[8], r1[8];
#pragma unroll
    for (int u = 0; u < 8; u++) {
        const int t = tq * 8 + u;
        const ulonglong2* xp = reinterpret_cast<const ulonglong2*>(&sx[t][0]);
        u64 a0 = 0, a1 = 0;
#pragma unroll
        for (int m = 0; m < 8; m++) {
            ulonglong2 xv = xp[m];
            a0 = ffma2(w0[2 * m],     xv.x, a0);
            a0 = ffma2(w0[2 * m + 1], xv.y, a0);
            a1 = ffma2(w1[2 * m],     xv.x, a1);
            a1 = ffma2(w1[2 * m + 1], xv.y, a1);
        }
        float lo, hi; upk2(a0, lo, hi); r0[u] = lo + hi + bs0;
        upk2(a1, lo, hi);               r1[u] = lo + hi + bs1;
    }

    float* out = dir ? g_xw1 : g_xw0;
    const int base0 = (b * HH + j0) * TT + t0 + tq * 8;
    const int base1 = (b * HH + j1) * TT + t0 + tq * 8;
    *(float4*)&out[base0]     = make_float4(r0[0], r0[1], r0[2], r0[3]);
    *(float4*)&out[base0 + 4] = make_float4(r0[4], r0[5], r0[6], r0[7]);
    *(float4*)&out[base1]     = make_float4(r1[0], r1[1], r1[2], r1[3]);
    *(float4*)&out[base1 + 4] = make_float4(r1[4], r1[5], r1[6], r1[7]);
}

// ============================================================================
// Kernel 2: recurrent scan. h_t = relu(xw_t + h_{t-1} @ W_hh^T), t-major I/O.
// Fast path (W_hh == I, exact runtime check): independent elementwise chains,
// thread = (dir, j) of batch blockIdx.x, contiguous float4 along t with
// double-buffered prefetch (8 LDG.128 in flight during the 256-cyc chain).
// General path: cooperative 64x64 matvec fallback (correct, slow).
// ============================================================================
__global__ __launch_bounds__(128) void scan_kernel(
    const float* __restrict__ Whhf, const float* __restrict__ Whhb)
{
    const int b   = blockIdx.x;
    const int tx  = threadIdx.x;
    const int dir = tx >> 6;
    const int j   = tx & 63;

    const float* W = dir ? Whhb : Whhf;

    __shared__ int sOK;
    if (tx == 0) sOK = 1;
    __syncthreads();
    {
        bool ok = true;
#pragma unroll
        for (int k = 0; k < HH; k++) {
            float want = (k == j) ? 1.0f : 0.0f;
            if (W[j * HH + k] != want) ok = false;
        }
        if (!ok) atomicAnd(&sOK, 0);
    }
    __syncthreads();

    const float* xw = (dir ? g_xw1 : g_xw0) + (size_t)(b * HH + j) * TT;
    float*       ho = (dir ? g_h1  : g_h0)  + (size_t)(b * HH + j) * TT;

    if (sOK) {
        const float4* xi = reinterpret_cast<const float4*>(xw);
        float4*       hw = reinterpret_cast<float4*>(ho);
        float h = 0.0f;
        float4 buf[2][8];
        constexpr int NG = TT / 32;   // 64 groups of 32 t

        if (dir == 0) {
#pragma unroll
            for (int u = 0; u < 8; u++) buf[0][u] = xi[u];
            for (int g = 0; g < NG; g++) {
                const int cb = g & 1;
                if (g + 1 < NG) {
#pragma unroll
                    for (int u = 0; u < 8; u++) buf[cb ^ 1][u] = xi[(g + 1) * 8 + u];
                }
                float* s = reinterpret_cast<float*>(buf[cb]);
#pragma unroll
                for (int i = 0; i < 32; i++) { h = fmaxf(s[i] + h, 0.0f); s[i] = h; }
#pragma unroll
                for (int u = 0; u < 8; u++) hw[g * 8 + u] = buf[cb][u];
            }
        } else {
#pragma unroll
            for (int u = 0; u < 8; u++) buf[1][u] = xi[(NG - 1) * 8 + u];
            for (int g = NG - 1; g >= 0; g--) {
                const int cb = g & 1;
                if (g > 0) {
#pragma unroll
                    for (int u = 0; u < 8; u++) buf[cb ^ 1][u] = xi[(g - 1) * 8 + u];
                }
                float* s = reinterpret_cast<float*>(buf[cb]);
#pragma unroll
                for (int i = 31; i >= 0; i--) { h = fmaxf(s[i] + h, 0.0f); s[i] = h; }
#pragma unroll
                for (int u = 0; u < 8; u++) hw[g * 8 + u] = buf[cb][u];
            }
        }
    } else {
        // general fallback: per-step 64x64 matvec (t-major indexing)
        __shared__ float sh[2][HH];
        float wrow[HH];
#pragma unroll
        for (int k = 0; k < HH; k++) wrow[k] = W[j * HH + k];
        sh[dir][j] = 0.0f;
        __syncthreads();
        for (int t = 0; t < TT; t++) {
            const int tt = dir ? (TT - 1 - t) : t;
            float acc = xw[tt];
#pragma unroll
            for (int k = 0; k < HH; k++) acc += wrow[k] * sh[dir][k];
            acc = fmaxf(acc, 0.0f);
            __syncthreads();
            sh[dir][j] = acc;
            __syncthreads();
            ho[tt] = acc;
        }
    }
}

// ============================================================================
// Kernel 3: MLP head.
// out[r] = ff1_b + sum_j ff1[j]*leaky(ff0_b[j] + sum_k ff0[j,k]*hcat[r,k])
// hcat row = [hf ; hb] (128 wide). h planes are t-major -> staged with an
// in-SMEM transpose (pitch 132 avoids staging conflicts). Compute: thread =
// (kseg 0..3, j-pair); the m-loop is ROTATED by 2*kseg so the 4 ksegs read
// disjoint bank groups ((33r + m + 2c) mod 8 distinct) — no LDS conflicts.
// ============================================================================
__global__ __launch_bounds__(256) void mlp_kernel(
    const float* __restrict__ ff0w, const float* __restrict__ ff0b,
    const float* __restrict__ ff1w, const float* __restrict__ ff1b,
    float* __restrict__ out)
{
    __shared__ __align__(16) float shh[8][132];   // padded pitch
    __shared__ float sPart[8][8];

    const int tx   = threadIdx.x;
    const int kseg = tx & 3;
    const int jp   = tx >> 2;
    const int j0   = jp * 2, j1 = j0 + 1;
    const int kb   = kseg * 32;
    const int warp = tx >> 5, lane = tx & 31;

    u64 wa[16], wb[16];
#pragma unroll
    for (int m = 0; m < 16; m++) {
        wa[m] = pk2(ff0w[j0 * 128 + kb + 2 * m], ff0w[j0 * 128 + kb + 2 * m + 1]);
        wb[m] = pk2(ff0w[j1 * 128 + kb + 2 * m], ff0w[j1 * 128 + kb + 2 * m + 1]);
    }
    const float b00 = ff0b[j0], b01 = ff0b[j1];
    const float f10 = ff1w[j0], f11 = ff1w[j1];
    const float f1b = ff1b[0];

    // staging map: thread -> (dir, j, 4-t half) of the 8-row tile
    const int sdir = tx >> 7;
    const int sj   = (tx >> 1) & 63;
    const int sth  = (tx & 1) * 4;
    const float* hplane = sdir ? g_h1 : g_h0;
    const int    scol   = sdir * 64 + sj;

    const int ntiles = NROWS / 8;
    for (int tile = blockIdx.x; tile < ntiles; tile += gridDim.x) {
        const int row0 = tile * 8;
        const int b    = row0 >> 11;          // TT = 2048
        const int t0   = row0 & (TT - 1);
        __syncthreads();
        {
            float4 v = *(const float4*)&hplane[(size_t)(b * HH + sj) * TT + t0 + sth];
            shh[sth + 0][scol] = v.x;
            shh[sth + 1][scol] = v.y;
            shh[sth + 2][scol] = v.z;
            shh[sth + 3][scol] = v.w;
        }
        __syncthreads();
#pragma unroll 1
        for (int r = 0; r < 8; r++) {
            const ulonglong2* hp = reinterpret_cast<const ulonglong2*>(&shh[r][kb]);
            u64 acc0 = 0, acc1 = 0;
#pragma unroll
            for (int m = 0; m < 8; m++) {
                const int mm = (m + 2 * kseg) & 7;   // bank-group rotation
                ulonglong2 hv = hp[mm];
                acc0 = ffma2(wa[2 * mm],     hv.x, acc0);
                acc0 = ffma2(wa[2 * mm + 1], hv.y, acc0);
                acc1 = ffma2(wb[2 * mm],     hv.x, acc1);
                acc1 = ffma2(wb[2 * mm + 1], hv.y, acc1);
            }
            float l0, h0, l1, h1;
            upk2(acc0, l0, h0); upk2(acc1, l1, h1);
            float z0 = l0 + h0, z1 = l1 + h1;
            z0 += __shfl_xor_sync(0xffffffffu, z0, 1);
            z0 += __shfl_xor_sync(0xffffffffu, z0, 2);
            z1 += __shfl_xor_sync(0xffffffffu, z1, 1);
            z1 += __shfl_xor_sync(0xffffffffu, z1, 2);
            z0 += b00; z1 += b01;
            float y0 = z0 > 0.0f ? z0 : 0.01f * z0;
            float y1 = z1 > 0.0f ? z1 : 0.01f * z1;
            float y = f10 * y0 + f11 * y1;
            y += __shfl_xor_sync(0xffffffffu, y, 4);
            y += __shfl_xor_sync(0xffffffffu, y, 8);
            y += __shfl_xor_sync(0xffffffffu, y, 16);
            if (lane == 0) sPart[warp][r] = y;
        }
        __syncthreads();
        if (tx < 8) {
            float s = 0.0f;
#pragma unroll
            for (int w = 0; w < 8; w++) s += sPart[w][tx];
            out[row0 + tx] = s + f1b;
        }
    }
}

// ============================================================================
extern "C" void kernel_launch(void* const* d_in, const int* in_sizes, int n_in,
                              void* d_out, int out_size)
{
    const float* x    = (const float*)d_in[0];
    const float* Wihf = (const float*)d_in[1];
    const float* Whhf = (const float*)d_in[2];
    const float* bihf = (const float*)d_in[3];
    const float* bhhf = (const float*)d_in[4];
    const float* Wihb = (const float*)d_in[5];
    const float* Whhb = (const float*)d_in[6];
    const float* bihb = (const float*)d_in[7];
    const float* bhhb = (const float*)d_in[8];
    const float* ff0w = (const float*)d_in[9];
    const float* ff0b = (const float*)d_in[10];
    const float* ff1w = (const float*)d_in[11];
    const float* ff1b = (const float*)d_in[12];

    proj_kernel<<<8192, 256>>>(x, Wihf, Wihb, bihf, bhhf, bihb, bhhb);
    scan_kernel<<<128, 128>>>(Whhf, Whhb);
    mlp_kernel<<<2048, 256>>>(ff0w, ff0b, ff1w, ff1b, (float*)d_out);
}

// round 4
// speedup vs baseline: 2.5583x; 1.4249x over previous
#include <cuda_runtime.h>
#include <cstdint>
#include <cstddef>

// Problem constants (fixed by the reference)
#define BB 128
#define TT 2048
#define II 32
#define HH 64
constexpr int NROWS  = BB * TT;        // 262144
constexpr int NELEM  = NROWS * HH;     // 16,777,216 per plane
constexpr int NCHAIN = BB * 2 * HH;    // 16384 scan chains
constexpr int CHK    = 8;              // chunks per chain (scan split)
constexpr int CLEN   = TT / CHK;       // 256

// Scratch (device globals — no runtime allocation allowed).
// xw / h planes are j-major: plane[b*TT + t][64]
__device__ float g_xw0[NELEM];
__device__ float g_xw1[NELEM];
__device__ float g_h0[NELEM];
__device__ float g_h1[NELEM];
__device__ float g_S  [NCHAIN * CHK];  // per-chunk sum of xw
__device__ float g_hin[NCHAIN * CHK];  // per-chunk incoming h

typedef unsigned long long u64;

// ---- packed f32x2 helpers (Blackwell sm_103a) ------------------------------
__device__ __forceinline__ u64 pk2(float lo, float hi) {
    u64 r; asm("mov.b64 %0, {%1, %2};" : "=l"(r) : "f"(lo), "f"(hi)); return r;
}
__device__ __forceinline__ void upk2(u64 v, float& lo, float& hi) {
    asm("mov.b64 {%0, %1}, %2;" : "=f"(lo), "=f"(hi) : "l"(v));
}
__device__ __forceinline__ u64 ffma2(u64 a, u64 b, u64 c) {
    u64 d; asm("fma.rn.f32x2 %0, %1, %2, %3;" : "=l"(d) : "l"(a), "l"(b), "l"(c)); return d;
}
__device__ __forceinline__ u64 add2(u64 a, u64 b) {
    u64 d; asm("add.rn.f32x2 %0, %1, %2;" : "=l"(d) : "l"(a), "l"(b)); return d;
}

__device__ __forceinline__ bool row_is_identity(const float* W, int j) {
    bool ok = true;
#pragma unroll
    for (int k = 0; k < HH; k++) ok &= (W[j * HH + k] == ((k == j) ? 1.0f : 0.0f));
    return ok;
}

// ============================================================================
// Kernel 1: input projection, j-major output.
// xw[d][b][t][j] = sum_i x[b,t,i]*W_ih_d[j,i] + b_ih_d[j] + b_hh_d[j]
// Block = (b, 32-t tile), 256 thr. Compute: lane = t, warp w handles 8 j-pair
// groups jpg = w*8+it (jpg<32 -> dir0, else dir1). x in per-lane registers
// (packed f32x2), weights warp-uniform from SMEM (broadcast). Results bounce
// through SMEM -> coalesced STG.128 (4 lines/instr).
// ============================================================================
__global__ __launch_bounds__(256) void proj_kernel(
    const float* __restrict__ x,
    const float* __restrict__ Wihf, const float* __restrict__ Wihb,
    const float* __restrict__ bihf, const float* __restrict__ bhhf,
    const float* __restrict__ bihb, const float* __restrict__ bhhb)
{
    __shared__ float sxT[II][33];      // x transposed, conflict-free both ways
    __shared__ u64   swpk[64][II];     // packed weight pairs per jpg
    __shared__ u64   sbias[64];
    __shared__ u64   sout[32 * 65];    // [t][jpg], pitch 65 u64

    const int tx = threadIdx.x;
    const int b  = blockIdx.x >> 6;
    const int t0 = (blockIdx.x & 63) * 32;

    // stage x transposed: sxT[i][t]
    {
        int tl = tx >> 3, c4 = (tx & 7) * 4;
        float4 v = *(const float4*)&x[(size_t)(b * TT + t0 + tl) * II + c4];
        sxT[c4 + 0][tl] = v.x; sxT[c4 + 1][tl] = v.y;
        sxT[c4 + 2][tl] = v.z; sxT[c4 + 3][tl] = v.w;
    }
    // stage packed weights: swpk[jpg][i] = {W[2jp][i], W[2jp+1][i]}
    {
        int jpg = tx >> 2, iq = tx & 3;
        const float* W = (jpg >= 32) ? Wihb : Wihf;
        int jl = (jpg & 31) * 2;
        const float* ra = &W[jl * II + iq * 8];
        const float* rb = &W[(jl + 1) * II + iq * 8];
        float4 a0 = *(const float4*)ra, a1 = *(const float4*)(ra + 4);
        float4 b0 = *(const float4*)rb, b1 = *(const float4*)(rb + 4);
        u64* dst = &swpk[jpg][iq * 8];
        dst[0] = pk2(a0.x, b0.x); dst[1] = pk2(a0.y, b0.y);
        dst[2] = pk2(a0.z, b0.z); dst[3] = pk2(a0.w, b0.w);
        dst[4] = pk2(a1.x, b1.x); dst[5] = pk2(a1.y, b1.y);
        dst[6] = pk2(a1.z, b1.z); dst[7] = pk2(a1.w, b1.w);
    }
    if (tx < 64) {
        int dir = tx >> 5, jl = (tx & 31) * 2;
        float s0 = dir ? (bihb[jl]     + bhhb[jl])     : (bihf[jl]     + bhhf[jl]);
        float s1 = dir ? (bihb[jl + 1] + bhhb[jl + 1]) : (bihf[jl + 1] + bhhf[jl + 1]);
        sbias[tx] = pk2(s0, s1);
    }
    __syncthreads();

    const int w = tx >> 5, lane = tx & 31;

    // x row for this lane's t, packed (x,x) for dual-j FFMA2
    u64 xpk[II];
#pragma unroll
    for (int i = 0; i < II; i++) { float xv = sxT[i][lane]; xpk[i] = pk2(xv, xv); }

#pragma unroll
    for (int it = 0; it < 8; it++) {
        const int jpg = w * 8 + it;
        u64 acca = sbias[jpg];     // warp-uniform broadcast
        u64 accb = 0ull;           // {0.f, 0.f}
#pragma unroll
        for (int i = 0; i < II; i += 2) {
            acca = ffma2(swpk[jpg][i],     xpk[i],     acca);
            accb = ffma2(swpk[jpg][i + 1], xpk[i + 1], accb);
        }
        sout[lane * 65 + jpg] = add2(acca, accb);
    }
    __syncthreads();

    // coalesced store phase: each warp instr writes one t row (4 lines)
#pragma unroll
    for (int v = 0; v < 4; v++) {
        const int t   = v * 8 + w;
        const int c32 = lane;
        u64 lo = sout[t * 65 + 2 * c32];
        u64 hi = sout[t * 65 + 2 * c32 + 1];
        float f0, f1, f2, f3; upk2(lo, f0, f1); upk2(hi, f2, f3);
        const int dir = c32 >> 4, j4 = (c32 & 15) * 4;
        float* plane = dir ? g_xw1 : g_xw0;
        *(float4*)&plane[(size_t)(b * TT + t0 + t) * HH + j4] = make_float4(f0, f1, f2, f3);
    }
}

// ============================================================================
// Scan, split into CHK chunks per chain (max-plus associative scan).
// pass1: per-chunk local scan with h_in=0 (writes h_local into h plane) and
//        per-chunk sum S. Fast path only if W_hh == I (exact); else one block
//        per (b,dir) runs the full-length general matvec scan.
// pass2: 8-step serial boundary scan per chain: h_in[c+1] = max(S_c + h_in_c,
//        h_local_last_c); stores h_in per chunk.
// pass3: h_t = max(S_t + h_in, h_local_t) (valid since h_in >= 0); chunk 0 and
//        chunks with h_in == 0 are exact no-ops and skipped.
// Block map (pass1/3): blk=(b,q); tx: j=tx&63, combo=q*4+(tx>>6); dir=combo>>3
// (blocks are dir-pure), chunk=combo&7. Warp = 32 consecutive j -> coalesced.
// ============================================================================
__global__ __launch_bounds__(256) void scan_pass1(
    const float* __restrict__ Whhf, const float* __restrict__ Whhb)
{
    const int blk = blockIdx.x;          // 512
    const int b = blk >> 2, q = blk & 3;
    const int tx = threadIdx.x;
    const int j = tx & 63;
    const int combo = q * 4 + (tx >> 6);
    const int dir = combo >> 3;
    const int chunk = combo & 7;
    const float* W = dir ? Whhb : Whhf;

    __shared__ int sOK;
    if (tx == 0) sOK = 1;
    __syncthreads();
    if (!row_is_identity(W, j)) atomicAnd(&sOK, 0);
    __syncthreads();

    const float* xw = dir ? g_xw1 : g_xw0;
    float*       hp = dir ? g_h1  : g_h0;

    if (sOK) {
        const int tstart = dir ? (TT - 1 - chunk * CLEN) : chunk * CLEN;
        const ptrdiff_t step = dir ? -(ptrdiff_t)HH : (ptrdiff_t)HH;
        const float* xp = xw + (size_t)(b * TT + tstart) * HH + j;
        float*       hw = hp + (size_t)(b * TT + tstart) * HH + j;
        float h = 0.0f, S = 0.0f;
        for (int g = 0; g < CLEN / 8; g++) {
            float v[8];
#pragma unroll
            for (int u = 0; u < 8; u++) v[u] = xp[step * u];
#pragma unroll
            for (int u = 0; u < 8; u++) {
                S += v[u];
                h = fmaxf(v[u] + h, 0.0f);
                hw[step * u] = h;
            }
            xp += step * 8; hw += step * 8;
        }
        g_S[((b * 128 + dir * 64 + j) << 3) + chunk] = S;
    } else {
        // general fallback: one block per (b,dir) does the full serial scan
        if (q != 0 && q != 2) return;
        __shared__ float shv[HH];
        float wrow[HH];
        if (tx < HH) {
#pragma unroll
            for (int k = 0; k < HH; k++) wrow[k] = W[j * HH + k];
            shv[j] = 0.0f;
        }
        __syncthreads();
        for (int t = 0; t < TT; t++) {
            const int tt = dir ? (TT - 1 - t) : t;
            float acc = 0.0f;
            if (tx < HH) {
                acc = xw[(size_t)(b * TT + tt) * HH + j];
#pragma unroll
                for (int k = 0; k < HH; k++) acc += wrow[k] * shv[k];
                acc = fmaxf(acc, 0.0f);
            }
            __syncthreads();
            if (tx < HH) {
                shv[j] = acc;
                hp[(size_t)(b * TT + tt) * HH + j] = acc;
            }
            __syncthreads();
        }
    }
}

__global__ __launch_bounds__(256) void scan_pass2(
    const float* __restrict__ Whhf, const float* __restrict__ Whhb)
{
    const int tx = threadIdx.x;
    const int chain = blockIdx.x * 256 + tx;   // 64 blocks
    const int j = chain & 63, dir = (chain >> 6) & 1, b = chain >> 7;

    __shared__ int sOKd[2];
    if (tx < 2) sOKd[tx] = 1;
    __syncthreads();
    {
        const int cd = (tx >> 6) & 1;
        const float* Wc = cd ? Whhb : Whhf;
        if (!row_is_identity(Wc, tx & 63)) atomicAnd(&sOKd[cd], 0);
    }
    __syncthreads();
    if (!sOKd[dir]) return;   // general path already wrote full h

    const float* hp = dir ? g_h1 : g_h0;
    float hin = 0.0f;
#pragma unroll
    for (int c = 0; c < CHK; c++) {
        g_hin[chain * CHK + c] = hin;
        const int tl = dir ? (TT - 1 - c * CLEN - (CLEN - 1)) : (c * CLEN + CLEN - 1);
        const float hl = hp[(size_t)(b * TT + tl) * HH + j];
        hin = fmaxf(g_S[chain * CHK + c] + hin, hl);
    }
}

__global__ __launch_bounds__(256) void scan_pass3(
    const float* __restrict__ Whhf, const float* __restrict__ Whhb)
{
    const int blk = blockIdx.x;
    const int b = blk >> 2, q = blk & 3;
    const int tx = threadIdx.x;
    const int j = tx & 63;
    const int combo = q * 4 + (tx >> 6);
    const int dir = combo >> 3;
    const int chunk = combo & 7;
    const float* W = dir ? Whhb : Whhf;

    __shared__ int sOK;
    if (tx == 0) sOK = 1;
    __syncthreads();
    if (!row_is_identity(W, j)) atomicAnd(&sOK, 0);
    __syncthreads();
    if (!sOK) return;
    if (chunk == 0) return;

    const int chain = b * 128 + dir * 64 + j;
    const float hin = g_hin[chain * CHK + chunk];
    if (hin == 0.0f) return;   // max(S_t+0, h_local)=h_local exactly — no-op

    const float* xw = dir ? g_xw1 : g_xw0;
    float*       hp = dir ? g_h1  : g_h0;
    const int tstart = dir ? (TT - 1 - chunk * CLEN) : chunk * CLEN;
    const ptrdiff_t step = dir ? -(ptrdiff_t)HH : (ptrdiff_t)HH;
    const float* xp = xw + (size_t)(b * TT + tstart) * HH + j;
    float*       hw = hp + (size_t)(b * TT + tstart) * HH + j;
    float S = 0.0f;
    for (int g = 0; g < CLEN / 8; g++) {
        float v[8], hl[8];
#pragma unroll
        for (int u = 0; u < 8; u++) v[u]  = xp[step * u];
#pragma unroll
        for (int u = 0; u < 8; u++) hl[u] = hw[step * u];
#pragma unroll
        for (int u = 0; u < 8; u++) {
            S += v[u];
            hw[step * u] = fmaxf(S + hin, hl[u]);
        }
        xp += step * 8; hw += step * 8;
    }
}

// ============================================================================
// Kernel 3: MLP head (unchanged compute from R3 — conflict-free rotation).
// Staging is now a straight coalesced copy from j-major h planes.
// ============================================================================
__global__ __launch_bounds__(256) void mlp_kernel(
    const float* __restrict__ ff0w, const float* __restrict__ ff0b,
    const float* __restrict__ ff1w, const float* __restrict__ ff1b,
    float* __restrict__ out)
{
    __shared__ __align__(16) float shh[8][132];   // padded pitch
    __shared__ float sPart[8][8];

    const int tx   = threadIdx.x;
    const int kseg = tx & 3;
    const int jp   = tx >> 2;
    const int j0   = jp * 2, j1 = j0 + 1;
    const int kb   = kseg * 32;
    const int warp = tx >> 5, lane = tx & 31;

    u64 wa[16], wb[16];
#pragma unroll
    for (int m = 0; m < 16; m++) {
        wa[m] = pk2(ff0w[j0 * 128 + kb + 2 * m], ff0w[j0 * 128 + kb + 2 * m + 1]);
        wb[m] = pk2(ff0w[j1 * 128 + kb + 2 * m], ff0w[j1 * 128 + kb + 2 * m + 1]);
    }
    const float b00 = ff0b[j0], b01 = ff0b[j1];
    const float f10 = ff1w[j0], f11 = ff1w[j1];
    const float f1b = ff1b[0];

    // staging map: thread -> (row r, dir, 4-j chunk)
    const int sr  = tx >> 5;
    const int scc = tx & 31;
    const int sdir = scc >> 4;
    const int sk4  = (scc & 15) * 4;
    const float* hplane = sdir ? g_h1 : g_h0;

    const int ntiles = NROWS / 8;
    for (int tile = blockIdx.x; tile < ntiles; tile += gridDim.x) {
        const int row0 = tile * 8;
        __syncthreads();
        {
            float4 v = *(const float4*)&hplane[(size_t)(row0 + sr) * HH + sk4];
            *(float4*)&shh[sr][sdir * 64 + sk4] = v;
        }
        __syncthreads();
#pragma unroll 1
        for (int r = 0; r < 8; r++) {
            const ulonglong2* hpv = reinterpret_cast<const ulonglong2*>(&shh[r][kb]);
            u64 acc0 = 0, acc1 = 0;
#pragma unroll
            for (int m = 0; m < 8; m++) {
                const int mm = (m + 2 * kseg) & 7;   // bank-group rotation
                ulonglong2 hv = hpv[mm];
                acc0 = ffma2(wa[2 * mm],     hv.x, acc0);
                acc0 = ffma2(wa[2 * mm + 1], hv.y, acc0);
                acc1 = ffma2(wb[2 * mm],     hv.x, acc1);
                acc1 = ffma2(wb[2 * mm + 1], hv.y, acc1);
            }
            float l0, h0, l1, h1;
            upk2(acc0, l0, h0); upk2(acc1, l1, h1);
            float z0 = l0 + h0, z1 = l1 + h1;
            z0 += __shfl_xor_sync(0xffffffffu, z0, 1);
            z0 += __shfl_xor_sync(0xffffffffu, z0, 2);
            z1 += __shfl_xor_sync(0xffffffffu, z1, 1);
            z1 += __shfl_xor_sync(0xffffffffu, z1, 2);
            z0 += b00; z1 += b01;
            float y0 = z0 > 0.0f ? z0 : 0.01f * z0;
            float y1 = z1 > 0.0f ? z1 : 0.01f * z1;
            float y = f10 * y0 + f11 * y1;
            y += __shfl_xor_sync(0xffffffffu, y, 4);
            y += __shfl_xor_sync(0xffffffffu, y, 8);
            y += __shfl_xor_sync(0xffffffffu, y, 16);
            if (lane == 0) sPart[warp][r] = y;
        }
        __syncthreads();
        if (tx < 8) {
            float s = 0.0f;
#pragma unroll
            for (int w = 0; w < 8; w++) s += sPart[w][tx];
            out[row0 + tx] = s + f1b;
        }
    }
}

// ============================================================================
extern "C" void kernel_launch(void* const* d_in, const int* in_sizes, int n_in,
                              void* d_out, int out_size)
{
    const float* x    = (const float*)d_in[0];
    const float* Wihf = (const float*)d_in[1];
    const float* Whhf = (const float*)d_in[2];
    const float* bihf = (const float*)d_in[3];
    const float* bhhf = (const float*)d_in[4];
    const float* Wihb = (const float*)d_in[5];
    const float* Whhb = (const float*)d_in[6];
    const float* bihb = (const float*)d_in[7];
    const float* bhhb = (const float*)d_in[8];
    const float* ff0w = (const float*)d_in[9];
    const float* ff0b = (const float*)d_in[10];
    const float* ff1w = (const float*)d_in[11];
    const float* ff1b = (const float*)d_in[12];

    proj_kernel<<<8192, 256>>>(x, Wihf, Wihb, bihf, bhhf, bihb, bhhb);
    scan_pass1<<<512, 256>>>(Whhf, Whhb);
    scan_pass2<<<64, 256>>>(Whhf, Whhb);
    scan_pass3<<<512, 256>>>(Whhf, Whhb);
    mlp_kernel<<<2048, 256>>>(ff0w, ff0b, ff1w, ff1b, (float*)d_out);
}